// round 12
// baseline (speedup 1.0000x reference)
#include <cuda_runtime.h>
#include <cstdint>
#include <cstddef>

// Problem dims
#define BB 2
#define MM 4096
#define NN 4096
#define KK 4096
#define KW 128              // 4096 bits = 128 u32 words per row
#define KW_CHUNK 64         // popc path: K in 2 chunks of 64 words
#define NT_I 32             // imma path: 32 K-tiles of 128 bytes
#define NI 8                // n-tiles [0,NI) -> IMMA, [NI,32) -> POPC

// Bit-packed signs, TRANSPOSED [b][kw][m]
__device__ __align__(16) uint32_t g_xb[(size_t)BB * KW * MM];   // 4 MB
__device__ __align__(16) uint32_t g_yb[(size_t)BB * KW * NN];   // 4 MB
// s8 signs, PRE-TILED+PRE-SWIZZLED: tile = 16KB contiguous, SW128 inside.
// x: all 32 m-tiles; y: only the NI n-tiles the IMMA path reads.
__device__ __align__(16) signed char g_xi8[(size_t)BB * MM * KK];
__device__ __align__(16) signed char g_yi8[(size_t)BB * (NI * 128) * KK];

// ---------------------------------------------------------------------------
// Pack 1 (R9-exact): fp32 -> 1-bit sign word, transposed [b][kw][m].
// ---------------------------------------------------------------------------
__global__ void pack_bits(const float* __restrict__ in, uint32_t* __restrict__ out,
                          int rows, int nwords) {
    int t = blockIdx.x * blockDim.x + threadIdx.x;
    if (t >= nwords) return;
    int m  = t % rows;
    int kw = (t / rows) % KW;
    int b  = t / (rows * KW);

    const float4* p = reinterpret_cast<const float4*>(
        in + ((size_t)b * rows + m) * KK + kw * 32);

    uint32_t w = 0;
    #pragma unroll
    for (int j = 0; j < 8; j++) {
        float4 v = p[j];
        w |= (__float_as_uint(v.x) >> 31) << (j * 4 + 0);
        w |= (__float_as_uint(v.y) >> 31) << (j * 4 + 1);
        w |= (__float_as_uint(v.z) >> 31) << (j * 4 + 2);
        w |= (__float_as_uint(v.w) >> 31) << (j * 4 + 3);
    }
    out[((size_t)b * KW + kw) * rows + m] = w;
}

// ---------------------------------------------------------------------------
// Pack 2 (R7-exact math): fp32 -> s8 +-1 into tiled+swizzled layout.
// rows_store = number of rows packed (tile rows); row_stride = tensor row count.
// ---------------------------------------------------------------------------
__global__ void pack_tiles(const float* __restrict__ in, signed char* __restrict__ out,
                           int rows_store, int row_stride, int total4) {
    int i = blockIdx.x * blockDim.x + threadIdx.x;
    if (i >= total4) return;
    const int k4r = KK / 4;
    int k = (i % k4r) * 4;
    int m = (i / k4r) % rows_store;
    int b = i / (k4r * rows_store);

    float4 v = reinterpret_cast<const float4*>(
        in + ((size_t)b * row_stride + m) * KK)[k >> 2];
    char4 c;
    c.x = (__float_as_uint(v.x) >> 31) ? (signed char)-1 : (signed char)1;
    c.y = (__float_as_uint(v.y) >> 31) ? (signed char)-1 : (signed char)1;
    c.z = (__float_as_uint(v.z) >> 31) ? (signed char)-1 : (signed char)1;
    c.w = (__float_as_uint(v.w) >> 31) ? (signed char)-1 : (signed char)1;

    size_t tile = ((size_t)b * (rows_store / 128) + (m >> 7)) * (KK / 128) + (k >> 7);
    uint32_t off = (uint32_t)((m & 127) * 128 + (k & 127));
    uint32_t sw  = off ^ ((off >> 3) & 0x70);
    *reinterpret_cast<char4*>(out + tile * 16384 + sw) = c;
}

// ---------------------------------------------------------------------------
// Shared helpers
// ---------------------------------------------------------------------------
static constexpr int I_STAGES   = 3;
static constexpr int I_STAGE_SZ = 32 * 1024;
static constexpr int SMEM_TOTAL = I_STAGES * I_STAGE_SZ;   // 98304 (covers popc 64K)

__device__ __forceinline__ void cp16(uint32_t dst, const void* src) {
    asm volatile("cp.async.cg.shared.global [%0], [%1], 16;" :: "r"(dst), "l"(src));
}
__device__ __forceinline__ void ldsm_x4(uint32_t addr, uint32_t& r0, uint32_t& r1,
                                        uint32_t& r2, uint32_t& r3) {
    asm volatile("ldmatrix.sync.aligned.m8n8.x4.shared.b16 {%0,%1,%2,%3}, [%4];"
                 : "=r"(r0), "=r"(r1), "=r"(r2), "=r"(r3) : "r"(addr));
}
__device__ __forceinline__ void mma_s8(int* c, const uint32_t* a, const uint32_t* b) {
    asm volatile(
        "mma.sync.aligned.m16n8k32.row.col.s32.s8.s8.s32 "
        "{%0,%1,%2,%3}, {%4,%5,%6,%7}, {%8,%9}, {%0,%1,%2,%3};"
        : "+r"(c[0]), "+r"(c[1]), "+r"(c[2]), "+r"(c[3])
        : "r"(a[0]), "r"(a[1]), "r"(a[2]), "r"(a[3]), "r"(b[0]), "r"(b[1]));
}
__device__ __forceinline__ uint32_t maj3(uint32_t a, uint32_t b, uint32_t c) {
    uint32_t r;
    asm("lop3.b32 %0, %1, %2, %3, 0xE8;" : "=r"(r) : "r"(a), "r"(b), "r"(c));
    return r;
}
__device__ __forceinline__ uint32_t xor3(uint32_t a, uint32_t b, uint32_t c) {
    uint32_t r;
    asm("lop3.b32 %0, %1, %2, %3, 0x96;" : "=r"(r) : "r"(a), "r"(b), "r"(c));
    return r;
}

// ---------------------------------------------------------------------------
// IMMA path: R4-validated cp.async/wait_group pipeline; stage loads are
// contiguous copies from the pre-swizzled tiles.
// ---------------------------------------------------------------------------
__device__ __forceinline__ void imma_path(uint32_t sb, float scale,
                                          float* __restrict__ out) {
    const int tid  = threadIdx.x;
    const int lane = tid & 31;
    const int wid  = tid >> 5;
    const int wm   = wid >> 2;
    const int wn   = wid & 3;
    const int tn = blockIdx.x, tm = blockIdx.y, b = blockIdx.z;

    const signed char* Abase = g_xi8 + (((size_t)b * 32 + tm) * 32) * 16384;
    const signed char* Bbase = g_yi8 + (((size_t)b * NI + tn) * 32) * 16384;

    auto load_stage = [&](int slot, int kt) {
        const uint32_t stA = sb + slot * I_STAGE_SZ;
        const uint32_t stB = stA + 16384;
        const signed char* As = Abase + (size_t)kt * 16384;
        const signed char* Bs = Bbase + (size_t)kt * 16384;
        #pragma unroll
        for (int i = 0; i < 4; i++) {
            int idx = tid + i * 256;            // 0..1023 (16B units)
            cp16(stA + idx * 16, As + idx * 16);
            cp16(stB + idx * 16, Bs + idx * 16);
        }
        asm volatile("cp.async.commit_group;" ::: "memory");
    };

    load_stage(0, 0);
    load_stage(1, 1);

    const int rowA_l = (lane & 15);
    const int hiA    = lane >> 4;
    const int rowB_l = (lane & 7) + ((lane >> 4) << 3);
    const int hiB    = (lane >> 3) & 1;

    int acc[4][4][4];
    #pragma unroll
    for (int i = 0; i < 4; i++)
        #pragma unroll
        for (int j = 0; j < 4; j++)
            #pragma unroll
            for (int r = 0; r < 4; r++) acc[i][j][r] = 0;

    for (int kt = 0; kt < NT_I; kt++) {
        asm volatile("cp.async.wait_group 1;" ::: "memory");
        __syncthreads();

        if (kt + 2 < NT_I) load_stage((kt + 2) % I_STAGES, kt + 2);
        else asm volatile("cp.async.commit_group;" ::: "memory");

        const uint32_t stA = sb + (kt % I_STAGES) * I_STAGE_SZ;
        const uint32_t stB = stA + 16384;

        #pragma unroll
        for (int ks = 0; ks < 4; ks++) {
            uint32_t a[4][4];
            #pragma unroll
            for (int mf = 0; mf < 4; mf++) {
                int r = wm * 64 + mf * 16 + rowA_l;
                int c = (2 * ks + hiA) ^ (r & 7);
                ldsm_x4(stA + r * 128 + c * 16, a[mf][0], a[mf][1], a[mf][2], a[mf][3]);
            }
            uint32_t bfr[4][2];
            #pragma unroll
            for (int p = 0; p < 2; p++) {
                int r = wn * 32 + p * 16 + rowB_l;
                int c = (2 * ks + hiB) ^ (r & 7);
                ldsm_x4(stB + r * 128 + c * 16,
                        bfr[2 * p][0], bfr[2 * p][1], bfr[2 * p + 1][0], bfr[2 * p + 1][1]);
            }
            #pragma unroll
            for (int mf = 0; mf < 4; mf++)
                #pragma unroll
                for (int nf = 0; nf < 4; nf++)
                    mma_s8(acc[mf][nf], a[mf], bfr[nf]);
        }
        __syncthreads();
    }

    const int mbase = tm * 128 + wm * 64 + (lane >> 2);
    const int nbase = tn * 128 + wn * 32 + (lane & 3) * 2;
    #pragma unroll
    for (int mf = 0; mf < 4; mf++) {
        #pragma unroll
        for (int nf = 0; nf < 4; nf++) {
            int m0 = mbase + mf * 16;
            int n0 = nbase + nf * 8;
            float2 v0, v1;
            v0.x = (float)acc[mf][nf][0] * scale;
            v0.y = (float)acc[mf][nf][1] * scale;
            v1.x = (float)acc[mf][nf][2] * scale;
            v1.y = (float)acc[mf][nf][3] * scale;
            *reinterpret_cast<float2*>(out + ((size_t)b * MM + m0) * NN + n0)     = v0;
            *reinterpret_cast<float2*>(out + ((size_t)b * MM + m0 + 8) * NN + n0) = v1;
        }
    }
}

// ---------------------------------------------------------------------------
// POPC path (R10-validated, byte-identical).
// ---------------------------------------------------------------------------
__device__ __forceinline__ void popc_path(uint32_t* smem, uint32_t sb, float scale,
                                          float* __restrict__ out) {
    uint32_t* As = smem;
    uint32_t* Bs = smem + KW_CHUNK * 128;
    const uint32_t sbB = sb + KW_CHUNK * 128 * 4;

    const int tid = threadIdx.x;
    const int tm8 = tid >> 4;
    const int tn8 = tid & 15;
    const int tn = blockIdx.x, tm = blockIdx.y, b = blockIdx.z;

    const uint32_t* Ag = g_xb + (size_t)b * KW * MM + (size_t)tm * 128;
    const uint32_t* Bg = g_yb + (size_t)b * KW * NN + (size_t)tn * 128;

    int acc[8][8];
    #pragma unroll
    for (int i = 0; i < 8; i++)
        #pragma unroll
        for (int j = 0; j < 8; j++) acc[i][j] = 0;

    #pragma unroll 1
    for (int ck = 0; ck < KK / (KW_CHUNK * 32); ck++) {
        #pragma unroll
        for (int v = 0; v < 8; v++) {
            int idx = tid + v * 256;
            int row = idx >> 5;
            int c4  = (idx & 31) * 4;
            cp16(sb  + (row * 128 + c4) * 4, Ag + (size_t)(ck * KW_CHUNK + row) * MM + c4);
            cp16(sbB + (row * 128 + c4) * 4, Bg + (size_t)(ck * KW_CHUNK + row) * NN + c4);
        }
        asm volatile("cp.async.commit_group;" ::: "memory");
        asm volatile("cp.async.wait_group 0;" ::: "memory");
        __syncthreads();

        #pragma unroll 1
        for (int g = 0; g < 21; g++) {
            const int kw = g * 3;
            uint4 a00 = *reinterpret_cast<const uint4*>(&As[kw * 128 + tm8 * 8]);
            uint4 a01 = *reinterpret_cast<const uint4*>(&As[kw * 128 + tm8 * 8 + 4]);
            uint4 a10 = *reinterpret_cast<const uint4*>(&As[(kw + 1) * 128 + tm8 * 8]);
            uint4 a11 = *reinterpret_cast<const uint4*>(&As[(kw + 1) * 128 + tm8 * 8 + 4]);
            uint4 a20 = *reinterpret_cast<const uint4*>(&As[(kw + 2) * 128 + tm8 * 8]);
            uint4 a21 = *reinterpret_cast<const uint4*>(&As[(kw + 2) * 128 + tm8 * 8 + 4]);
            uint32_t av0[8] = {a00.x, a00.y, a00.z, a00.w, a01.x, a01.y, a01.z, a01.w};
            uint32_t av1[8] = {a10.x, a10.y, a10.z, a10.w, a11.x, a11.y, a11.z, a11.w};
            uint32_t av2[8] = {a20.x, a20.y, a20.z, a20.w, a21.x, a21.y, a21.z, a21.w};

            #pragma unroll
            for (int h = 0; h < 2; h++) {
                uint4 b0 = *reinterpret_cast<const uint4*>(&Bs[kw * 128 + tn8 * 8 + h * 4]);
                uint4 b1 = *reinterpret_cast<const uint4*>(&Bs[(kw + 1) * 128 + tn8 * 8 + h * 4]);
                uint4 b2 = *reinterpret_cast<const uint4*>(&Bs[(kw + 2) * 128 + tn8 * 8 + h * 4]);
                uint32_t bv0[4] = {b0.x, b0.y, b0.z, b0.w};
                uint32_t bv1[4] = {b1.x, b1.y, b1.z, b1.w};
                uint32_t bv2[4] = {b2.x, b2.y, b2.z, b2.w};
                #pragma unroll
                for (int i = 0; i < 8; i++) {
                    #pragma unroll
                    for (int j = 0; j < 4; j++) {
                        uint32_t x0 = av0[i] ^ bv0[j];
                        uint32_t x1 = av1[i] ^ bv1[j];
                        uint32_t x2 = av2[i] ^ bv2[j];
                        uint32_t s  = xor3(x0, x1, x2);
                        uint32_t c  = maj3(x0, x1, x2);
                        acc[i][h * 4 + j] += __popc(s) + 2 * __popc(c);
                    }
                }
            }
        }
        {
            const int kw = 63;
            uint4 a0 = *reinterpret_cast<const uint4*>(&As[kw * 128 + tm8 * 8]);
            uint4 a1 = *reinterpret_cast<const uint4*>(&As[kw * 128 + tm8 * 8 + 4]);
            uint4 b0 = *reinterpret_cast<const uint4*>(&Bs[kw * 128 + tn8 * 8]);
            uint4 b1 = *reinterpret_cast<const uint4*>(&Bs[kw * 128 + tn8 * 8 + 4]);
            uint32_t av[8] = {a0.x, a0.y, a0.z, a0.w, a1.x, a1.y, a1.z, a1.w};
            uint32_t bv[8] = {b0.x, b0.y, b0.z, b0.w, b1.x, b1.y, b1.z, b1.w};
            #pragma unroll
            for (int i = 0; i < 8; i++)
                #pragma unroll
                for (int j = 0; j < 8; j++)
                    acc[i][j] += __popc(av[i] ^ bv[j]);
        }
        __syncthreads();
    }

    const int m0 = tm * 128 + tm8 * 8;
    const int n0 = tn * 128 + tn8 * 8;
    #pragma unroll
    for (int i = 0; i < 8; i++) {
        float* orow = out + ((size_t)b * MM + m0 + i) * NN + n0;
        float4 v0, v1;
        v0.x = (float)(KK - 2 * acc[i][0]) * scale;
        v0.y = (float)(KK - 2 * acc[i][1]) * scale;
        v0.z = (float)(KK - 2 * acc[i][2]) * scale;
        v0.w = (float)(KK - 2 * acc[i][3]) * scale;
        v1.x = (float)(KK - 2 * acc[i][4]) * scale;
        v1.y = (float)(KK - 2 * acc[i][5]) * scale;
        v1.z = (float)(KK - 2 * acc[i][6]) * scale;
        v1.w = (float)(KK - 2 * acc[i][7]) * scale;
        *reinterpret_cast<float4*>(orow)     = v0;
        *reinterpret_cast<float4*>(orow + 4) = v1;
    }
}

// ---------------------------------------------------------------------------
// Hybrid dispatch kernel
// ---------------------------------------------------------------------------
__global__ void __launch_bounds__(256, 2)
bingemm_hybrid(const float* __restrict__ xclip, const float* __restrict__ yclip,
               float* __restrict__ out) {
    extern __shared__ __align__(1024) char smem[];
    uint32_t sb;
    asm("{ .reg .u64 t; cvta.to.shared.u64 t, %1; cvt.u32.u64 %0, t; }" : "=r"(sb) : "l"(smem));
    const float scale = xclip[0] * yclip[0];

    if (blockIdx.x < NI) {
        imma_path(sb, scale, out);
    } else {
        popc_path(reinterpret_cast<uint32_t*>(smem), sb, scale, out);
    }
}

// ---------------------------------------------------------------------------
// Launch
// ---------------------------------------------------------------------------
extern "C" void kernel_launch(void* const* d_in, const int* in_sizes, int n_in,
                              void* d_out, int out_size) {
    const float* x     = (const float*)d_in[0];
    const float* y     = (const float*)d_in[1];
    const float* xclip = (const float*)d_in[2];
    const float* yclip = (const float*)d_in[3];
    float* out = (float*)d_out;

    uint32_t *xb, *yb;
    signed char *xi8, *yi8;
    cudaGetSymbolAddress((void**)&xb, g_xb);
    cudaGetSymbolAddress((void**)&yb, g_yb);
    cudaGetSymbolAddress((void**)&xi8, g_xi8);
    cudaGetSymbolAddress((void**)&yi8, g_yi8);

    const int nwords = BB * KW * MM;
    pack_bits<<<(nwords + 255) / 256, 256>>>(x, xb, MM, nwords);
    pack_bits<<<(nwords + 255) / 256, 256>>>(y, yb, NN, nwords);

    const int n4x = BB * MM * (KK / 4);
    pack_tiles<<<(n4x + 255) / 256, 256>>>(x, xi8, MM, MM, n4x);
    const int n4y = BB * (NI * 128) * (KK / 4);
    pack_tiles<<<(n4y + 255) / 256, 256>>>(y, yi8, NI * 128, NN, n4y);

    cudaFuncSetAttribute(bingemm_hybrid, cudaFuncAttributeMaxDynamicSharedMemorySize, SMEM_TOTAL);
    dim3 grid(NN / 128, MM / 128, BB);
    bingemm_hybrid<<<grid, 256, SMEM_TOTAL>>>(xclip, yclip, out);
}

// round 14
// speedup vs baseline: 1.3187x; 1.3187x over previous
#include <cuda_runtime.h>
#include <cstdint>
#include <cstddef>

// Problem dims
#define BB 2
#define MM 4096
#define NN 4096
#define KK 4096
#define KW 128              // 4096 bits = 128 u32 words per row
#define KW_CHUNK 64         // K processed in 2 chunks of 64 words

// Bit-packed signs, TRANSPOSED [b][kw][m]
__device__ __align__(16) uint32_t g_xb[(size_t)BB * KW * MM];   // 4 MB
__device__ __align__(16) uint32_t g_yb[(size_t)BB * KW * NN];   // 4 MB

// ---------------------------------------------------------------------------
// Dual pack: one launch packs BOTH tensors (overlaps their DRAM streams).
// One thread per output word (R9-validated math).
// ---------------------------------------------------------------------------
__global__ void pack_bits2(const float* __restrict__ x, const float* __restrict__ y,
                           uint32_t* __restrict__ xb, uint32_t* __restrict__ yb,
                           int nwords) {
    int t = blockIdx.x * blockDim.x + threadIdx.x;
    const float* in;
    uint32_t* out;
    int tt;
    if (t < nwords)      { in = x; out = xb; tt = t; }
    else if (t < 2 * nwords) { in = y; out = yb; tt = t - nwords; }
    else return;

    int m  = tt % MM;
    int kw = (tt / MM) % KW;
    int b  = tt / (MM * KW);

    const float4* p = reinterpret_cast<const float4*>(
        in + ((size_t)b * MM + m) * KK + kw * 32);

    uint32_t w = 0;
    #pragma unroll
    for (int j = 0; j < 8; j++) {
        float4 v = p[j];
        w |= (__float_as_uint(v.x) >> 31) << (j * 4 + 0);
        w |= (__float_as_uint(v.y) >> 31) << (j * 4 + 1);
        w |= (__float_as_uint(v.z) >> 31) << (j * 4 + 2);
        w |= (__float_as_uint(v.w) >> 31) << (j * 4 + 3);
    }
    out[((size_t)b * KW + kw) * MM + m] = w;
}

// ---------------------------------------------------------------------------
// POPC GEMM, two-level 9:4 carry-save:
//   popc sum of 9 xor-words = popc(S) + 2popc(Cs) + 2popc(Sc) + 4popc(Cc)
// CTA tile 128x128, 256 threads, 8x8 outputs/thread.
// Accumulators PACKED: acc[i][jp] = cnt(col jp) | cnt(col jp+4) << 16.
// Load/sync skeleton identical to R10.
// ---------------------------------------------------------------------------
static constexpr int SMEM_TOTAL = 2 * KW_CHUNK * 128 * 4;   // 65536

__device__ __forceinline__ void cp16(uint32_t dst, const void* src) {
    asm volatile("cp.async.cg.shared.global [%0], [%1], 16;" :: "r"(dst), "l"(src));
}
__device__ __forceinline__ uint32_t maj3(uint32_t a, uint32_t b, uint32_t c) {
    uint32_t r;
    asm("lop3.b32 %0, %1, %2, %3, 0xE8;" : "=r"(r) : "r"(a), "r"(b), "r"(c));
    return r;
}
__device__ __forceinline__ uint32_t xor3(uint32_t a, uint32_t b, uint32_t c) {
    uint32_t r;
    asm("lop3.b32 %0, %1, %2, %3, 0x96;" : "=r"(r) : "r"(a), "r"(b), "r"(c));
    return r;
}

__global__ void __launch_bounds__(256, 2)
bingemm_popc(const float* __restrict__ xclip, const float* __restrict__ yclip,
             float* __restrict__ out) {
    extern __shared__ __align__(16) uint32_t smem[];
    uint32_t* As = smem;                    // [kw][m]  64 x 128
    uint32_t* Bs = smem + KW_CHUNK * 128;   // [kw][n]  64 x 128
    uint32_t sb;
    asm("{ .reg .u64 t; cvta.to.shared.u64 t, %1; cvt.u32.u64 %0, t; }" : "=r"(sb) : "l"(smem));
    const uint32_t sbB = sb + KW_CHUNK * 128 * 4;

    const int tid = threadIdx.x;
    const int tm8 = tid >> 4;     // 0..15 -> 8 m-rows
    const int tn8 = tid & 15;     // 0..15 -> 8 n-cols
    const int tn = blockIdx.x, tm = blockIdx.y, b = blockIdx.z;

    const uint32_t* Ag = g_xb + (size_t)b * KW * MM + (size_t)tm * 128;
    const uint32_t* Bg = g_yb + (size_t)b * KW * NN + (size_t)tn * 128;

    // Packed accumulators: lo16 = col (tn8*8 + jp), hi16 = col (tn8*8 + 4 + jp)
    uint32_t acc[8][4];
    #pragma unroll
    for (int i = 0; i < 8; i++)
        #pragma unroll
        for (int j = 0; j < 4; j++) acc[i][j] = 0;

    #pragma unroll 1
    for (int ck = 0; ck < KK / (KW_CHUNK * 32); ck++) {     // 2 chunks
        // --- load chunk (R10-identical) ---
        #pragma unroll
        for (int v = 0; v < 8; v++) {
            int idx = tid + v * 256;
            int row = idx >> 5;
            int c4  = (idx & 31) * 4;
            cp16(sb  + (row * 128 + c4) * 4, Ag + (size_t)(ck * KW_CHUNK + row) * MM + c4);
            cp16(sbB + (row * 128 + c4) * 4, Bg + (size_t)(ck * KW_CHUNK + row) * NN + c4);
        }
        asm volatile("cp.async.commit_group;" ::: "memory");
        asm volatile("cp.async.wait_group 0;" ::: "memory");
        __syncthreads();

        // --- compute: 7 groups of 9 kw (two-level CSA) + 1 leftover ---
        #pragma unroll 1
        for (int g = 0; g < 7; g++) {
            const int kw = g * 9;
            #pragma unroll
            for (int ib = 0; ib < 2; ib++) {
                uint32_t av[9][4];
                #pragma unroll
                for (int r = 0; r < 9; r++) {
                    uint4 t = *reinterpret_cast<const uint4*>(
                        &As[(kw + r) * 128 + tm8 * 8 + ib * 4]);
                    av[r][0] = t.x; av[r][1] = t.y; av[r][2] = t.z; av[r][3] = t.w;
                }
                #pragma unroll
                for (int jb = 0; jb < 2; jb++) {
                    uint32_t bv[9][4];
                    #pragma unroll
                    for (int r = 0; r < 9; r++) {
                        uint4 t = *reinterpret_cast<const uint4*>(
                            &Bs[(kw + r) * 128 + tn8 * 8 + jb * 4]);
                        bv[r][0] = t.x; bv[r][1] = t.y; bv[r][2] = t.z; bv[r][3] = t.w;
                    }
                    #pragma unroll
                    for (int ii = 0; ii < 4; ii++) {
                        #pragma unroll
                        for (int jj = 0; jj < 4; jj++) {
                            // level 1: three 3:2 compressors over 9 xor-words
                            uint32_t x0 = av[0][ii] ^ bv[0][jj];
                            uint32_t x1 = av[1][ii] ^ bv[1][jj];
                            uint32_t x2 = av[2][ii] ^ bv[2][jj];
                            uint32_t s0 = xor3(x0, x1, x2);
                            uint32_t c0 = maj3(x0, x1, x2);
                            uint32_t x3 = av[3][ii] ^ bv[3][jj];
                            uint32_t x4 = av[4][ii] ^ bv[4][jj];
                            uint32_t x5 = av[5][ii] ^ bv[5][jj];
                            uint32_t s1 = xor3(x3, x4, x5);
                            uint32_t c1 = maj3(x3, x4, x5);
                            uint32_t x6 = av[6][ii] ^ bv[6][jj];
                            uint32_t x7 = av[7][ii] ^ bv[7][jj];
                            uint32_t x8 = av[8][ii] ^ bv[8][jj];
                            uint32_t s2 = xor3(x6, x7, x8);
                            uint32_t c2 = maj3(x6, x7, x8);
                            // level 2
                            uint32_t S  = xor3(s0, s1, s2);   // weight 1
                            uint32_t Cs = maj3(s0, s1, s2);   // weight 2
                            uint32_t Sc = xor3(c0, c1, c2);   // weight 2
                            uint32_t Cc = maj3(c0, c1, c2);   // weight 4
                            uint32_t w = __popc(S) + 2 * (__popc(Cs) + __popc(Sc))
                                       + 4 * __popc(Cc);
                            if (jb == 0) acc[ib * 4 + ii][jj] += w;
                            else         acc[ib * 4 + ii][jj] += (w << 16);
                        }
                    }
                }
            }
        }
        // leftover word kw = 63
        {
            const int kw = 63;
            uint4 a0 = *reinterpret_cast<const uint4*>(&As[kw * 128 + tm8 * 8]);
            uint4 a1 = *reinterpret_cast<const uint4*>(&As[kw * 128 + tm8 * 8 + 4]);
            uint4 b0 = *reinterpret_cast<const uint4*>(&Bs[kw * 128 + tn8 * 8]);
            uint4 b1 = *reinterpret_cast<const uint4*>(&Bs[kw * 128 + tn8 * 8 + 4]);
            uint32_t av[8] = {a0.x, a0.y, a0.z, a0.w, a1.x, a1.y, a1.z, a1.w};
            uint32_t bv[8] = {b0.x, b0.y, b0.z, b0.w, b1.x, b1.y, b1.z, b1.w};
            #pragma unroll
            for (int i = 0; i < 8; i++) {
                #pragma unroll
                for (int jj = 0; jj < 4; jj++) {
                    acc[i][jj] += __popc(av[i] ^ bv[jj]);
                    acc[i][jj] += __popc(av[i] ^ bv[jj + 4]) << 16;
                }
            }
        }
        __syncthreads();   // before next chunk overwrites smem
    }

    // --- epilogue: unpack, dot = KK - 2*cnt, scale, store ---
    const float scale = xclip[0] * yclip[0];
    const int m0 = tm * 128 + tm8 * 8;
    const int n0 = tn * 128 + tn8 * 8;

    #pragma unroll
    for (int i = 0; i < 8; i++) {
        float* orow = out + ((size_t)b * MM + m0 + i) * NN + n0;
        float4 v0, v1;
        v0.x = (float)(KK - 2 * (int)(acc[i][0] & 0xFFFF)) * scale;
        v0.y = (float)(KK - 2 * (int)(acc[i][1] & 0xFFFF)) * scale;
        v0.z = (float)(KK - 2 * (int)(acc[i][2] & 0xFFFF)) * scale;
        v0.w = (float)(KK - 2 * (int)(acc[i][3] & 0xFFFF)) * scale;
        v1.x = (float)(KK - 2 * (int)(acc[i][0] >> 16)) * scale;
        v1.y = (float)(KK - 2 * (int)(acc[i][1] >> 16)) * scale;
        v1.z = (float)(KK - 2 * (int)(acc[i][2] >> 16)) * scale;
        v1.w = (float)(KK - 2 * (int)(acc[i][3] >> 16)) * scale;
        *reinterpret_cast<float4*>(orow)     = v0;
        *reinterpret_cast<float4*>(orow + 4) = v1;
    }
}

// ---------------------------------------------------------------------------
// Launch
// ---------------------------------------------------------------------------
extern "C" void kernel_launch(void* const* d_in, const int* in_sizes, int n_in,
                              void* d_out, int out_size) {
    const float* x     = (const float*)d_in[0];
    const float* y     = (const float*)d_in[1];
    const float* xclip = (const float*)d_in[2];
    const float* yclip = (const float*)d_in[3];
    float* out = (float*)d_out;

    uint32_t *xb, *yb;
    cudaGetSymbolAddress((void**)&xb, g_xb);
    cudaGetSymbolAddress((void**)&yb, g_yb);

    const int nwords = BB * KW * MM;                    // 1,048,576 per tensor
    pack_bits2<<<(2 * nwords + 255) / 256, 256>>>(x, y, xb, yb, nwords);

    cudaFuncSetAttribute(bingemm_popc, cudaFuncAttributeMaxDynamicSharedMemorySize, SMEM_TOTAL);
    dim3 grid(NN / 128, MM / 128, BB);
    bingemm_popc<<<grid, 256, SMEM_TOTAL>>>(xclip, yclip, out);
}

// round 15
// speedup vs baseline: 1.3795x; 1.0462x over previous
#include <cuda_runtime.h>
#include <cstdint>
#include <cstddef>

// Problem dims
#define BB 2
#define MM 4096
#define NN 4096
#define KK 4096
#define KW 128              // 4096 bits = 128 u32 words per row
#define KW_CHUNK 64         // K processed in 2 chunks of 64 words

// Bit-packed signs, TRANSPOSED [b][kw][m]
__device__ __align__(16) uint32_t g_xb[(size_t)BB * KW * MM];   // 4 MB
__device__ __align__(16) uint32_t g_yb[(size_t)BB * KW * NN];   // 4 MB

// ---------------------------------------------------------------------------
// Dual pack (R14-validated): one launch packs BOTH tensors.
// ---------------------------------------------------------------------------
__global__ void pack_bits2(const float* __restrict__ x, const float* __restrict__ y,
                           uint32_t* __restrict__ xb, uint32_t* __restrict__ yb,
                           int nwords) {
    int t = blockIdx.x * blockDim.x + threadIdx.x;
    const float* in;
    uint32_t* out;
    int tt;
    if (t < nwords)      { in = x; out = xb; tt = t; }
    else if (t < 2 * nwords) { in = y; out = yb; tt = t - nwords; }
    else return;

    int m  = tt % MM;
    int kw = (tt / MM) % KW;
    int b  = tt / (MM * KW);

    const float4* p = reinterpret_cast<const float4*>(
        in + ((size_t)b * MM + m) * KK + kw * 32);

    uint32_t w = 0;
    #pragma unroll
    for (int j = 0; j < 8; j++) {
        float4 v = p[j];
        w |= (__float_as_uint(v.x) >> 31) << (j * 4 + 0);
        w |= (__float_as_uint(v.y) >> 31) << (j * 4 + 1);
        w |= (__float_as_uint(v.z) >> 31) << (j * 4 + 2);
        w |= (__float_as_uint(v.w) >> 31) << (j * 4 + 3);
    }
    out[((size_t)b * KW + kw) * MM + m] = w;
}

// ---------------------------------------------------------------------------
// POPC GEMM, 9:4 CSA with parity pre-transform:
//  - smem triple rows (3t+2) overwritten with parity r0^r1^r2 once per chunk
//  - per pair: s_g = a2'[ii]^b2'[jj] (1 XOR); maj via LOP3 0xD4 (x0,x1,s)
//  Sum of 9 popc = popc(S) + 2popc(Cs) + 2popc(Sc) + 4popc(Cc).
// CTA tile 128x128, 256 threads, 8x8 outputs/thread, packed 16-bit accs.
// ---------------------------------------------------------------------------
static constexpr int SMEM_TOTAL = 2 * KW_CHUNK * 128 * 4;   // 65536

__device__ __forceinline__ void cp16(uint32_t dst, const void* src) {
    asm volatile("cp.async.cg.shared.global [%0], [%1], 16;" :: "r"(dst), "l"(src));
}
// maj(a,b,a^b^c) = (a&b)|((a^b)&~c)  -> LOP3 immediate 0xD4
__device__ __forceinline__ uint32_t majp(uint32_t a, uint32_t b, uint32_t s) {
    uint32_t r;
    asm("lop3.b32 %0, %1, %2, %3, 0xD4;" : "=r"(r) : "r"(a), "r"(b), "r"(s));
    return r;
}
__device__ __forceinline__ uint32_t xor3(uint32_t a, uint32_t b, uint32_t c) {
    uint32_t r;
    asm("lop3.b32 %0, %1, %2, %3, 0x96;" : "=r"(r) : "r"(a), "r"(b), "r"(c));
    return r;
}

__global__ void __launch_bounds__(256, 2)
bingemm_popc(const float* __restrict__ xclip, const float* __restrict__ yclip,
             float* __restrict__ out) {
    extern __shared__ __align__(16) uint32_t smem[];
    uint32_t* As = smem;                    // [kw][m]  64 x 128
    uint32_t* Bs = smem + KW_CHUNK * 128;   // [kw][n]  64 x 128
    uint32_t sb;
    asm("{ .reg .u64 t; cvta.to.shared.u64 t, %1; cvt.u32.u64 %0, t; }" : "=r"(sb) : "l"(smem));
    const uint32_t sbB = sb + KW_CHUNK * 128 * 4;

    const int tid = threadIdx.x;
    const int tm8 = tid >> 4;     // 0..15 -> 8 m-rows
    const int tn8 = tid & 15;     // 0..15 -> 8 n-cols
    const int tn = blockIdx.x, tm = blockIdx.y, b = blockIdx.z;

    const uint32_t* Ag = g_xb + (size_t)b * KW * MM + (size_t)tm * 128;
    const uint32_t* Bg = g_yb + (size_t)b * KW * NN + (size_t)tn * 128;

    // Packed accumulators: lo16 = col (tn8*8 + jp), hi16 = col (tn8*8 + 4 + jp)
    uint32_t acc[8][4];
    #pragma unroll
    for (int i = 0; i < 8; i++)
        #pragma unroll
        for (int j = 0; j < 4; j++) acc[i][j] = 0;

    #pragma unroll 1
    for (int ck = 0; ck < KK / (KW_CHUNK * 32); ck++) {     // 2 chunks
        // --- load chunk (R10/R14-identical) ---
        #pragma unroll
        for (int v = 0; v < 8; v++) {
            int idx = tid + v * 256;
            int row = idx >> 5;
            int c4  = (idx & 31) * 4;
            cp16(sb  + (row * 128 + c4) * 4, Ag + (size_t)(ck * KW_CHUNK + row) * MM + c4);
            cp16(sbB + (row * 128 + c4) * 4, Bg + (size_t)(ck * KW_CHUNK + row) * NN + c4);
        }
        asm volatile("cp.async.commit_group;" ::: "memory");
        asm volatile("cp.async.wait_group 0;" ::: "memory");
        __syncthreads();

        // --- parity pre-transform: rows 3t+2 (t=0..20) := r0^r1^r2, both ops ---
        // 21 triples x 128 cols x 2 operands = 5376 words = 21 per thread.
        // Writes touch only rows 3t+2; reads of those rows only by their own
        // writer -> no cross-thread race within the phase.
        #pragma unroll
        for (int k = 0; k < 21; k++) {
            int w   = tid + k * 256;            // 0..5375
            int op  = (w >= 2688) ? 1 : 0;
            int rem = w - op * 2688;
            int t   = rem >> 7;                 // triple 0..20
            int col = rem & 127;
            uint32_t* base = op ? Bs : As;
            uint32_t r0 = base[(3 * t + 0) * 128 + col];
            uint32_t r1 = base[(3 * t + 1) * 128 + col];
            uint32_t r2 = base[(3 * t + 2) * 128 + col];
            base[(3 * t + 2) * 128 + col] = xor3(r0, r1, r2);
        }
        __syncthreads();

        // --- compute: 7 groups of 9 kw + leftover word 63 ---
        #pragma unroll 1
        for (int g = 0; g < 7; g++) {
            const int kw = g * 9;
            #pragma unroll
            for (int ib = 0; ib < 2; ib++) {
                uint32_t av[9][4];
                #pragma unroll
                for (int r = 0; r < 9; r++) {
                    uint4 t = *reinterpret_cast<const uint4*>(
                        &As[(kw + r) * 128 + tm8 * 8 + ib * 4]);
                    av[r][0] = t.x; av[r][1] = t.y; av[r][2] = t.z; av[r][3] = t.w;
                }
                #pragma unroll
                for (int jb = 0; jb < 2; jb++) {
                    uint32_t bv[9][4];
                    #pragma unroll
                    for (int r = 0; r < 9; r++) {
                        uint4 t = *reinterpret_cast<const uint4*>(
                            &Bs[(kw + r) * 128 + tn8 * 8 + jb * 4]);
                        bv[r][0] = t.x; bv[r][1] = t.y; bv[r][2] = t.z; bv[r][3] = t.w;
                    }
                    #pragma unroll
                    for (int ii = 0; ii < 4; ii++) {
                        #pragma unroll
                        for (int jj = 0; jj < 4; jj++) {
                            // triple 0: rows 0,1 raw; row 2 = parity
                            uint32_t x0 = av[0][ii] ^ bv[0][jj];
                            uint32_t x1 = av[1][ii] ^ bv[1][jj];
                            uint32_t s0 = av[2][ii] ^ bv[2][jj];
                            uint32_t c0 = majp(x0, x1, s0);
                            // triple 1
                            uint32_t x3 = av[3][ii] ^ bv[3][jj];
                            uint32_t x4 = av[4][ii] ^ bv[4][jj];
                            uint32_t s1 = av[5][ii] ^ bv[5][jj];
                            uint32_t c1 = majp(x3, x4, s1);
                            // triple 2
                            uint32_t x6 = av[6][ii] ^ bv[6][jj];
                            uint32_t x7 = av[7][ii] ^ bv[7][jj];
                            uint32_t s2 = av[8][ii] ^ bv[8][jj];
                            uint32_t c2 = majp(x6, x7, s2);
                            // level 2
                            uint32_t S  = xor3(s0, s1, s2);   // weight 1
                            uint32_t Cs = majp(s0, s1, S);    // weight 2
                            uint32_t Sc = xor3(c0, c1, c2);   // weight 2
                            uint32_t Cc = majp(c0, c1, Sc);   // weight 4
                            uint32_t w = __popc(S) + 2 * (__popc(Cs) + __popc(Sc))
                                       + 4 * __popc(Cc);
                            if (jb == 0) acc[ib * 4 + ii][jj] += w;
                            else         acc[ib * 4 + ii][jj] += (w << 16);
                        }
                    }
                }
            }
        }
        // leftover word kw = 63 (untouched by the transform)
        {
            const int kw = 63;
            uint4 a0 = *reinterpret_cast<const uint4*>(&As[kw * 128 + tm8 * 8]);
            uint4 a1 = *reinterpret_cast<const uint4*>(&As[kw * 128 + tm8 * 8 + 4]);
            uint4 b0 = *reinterpret_cast<const uint4*>(&Bs[kw * 128 + tn8 * 8]);
            uint4 b1 = *reinterpret_cast<const uint4*>(&Bs[kw * 128 + tn8 * 8 + 4]);
            uint32_t av[8] = {a0.x, a0.y, a0.z, a0.w, a1.x, a1.y, a1.z, a1.w};
            uint32_t bv[8] = {b0.x, b0.y, b0.z, b0.w, b1.x, b1.y, b1.z, b1.w};
            #pragma unroll
            for (int i = 0; i < 8; i++) {
                #pragma unroll
                for (int jj = 0; jj < 4; jj++) {
                    acc[i][jj] += __popc(av[i] ^ bv[jj]);
                    acc[i][jj] += __popc(av[i] ^ bv[jj + 4]) << 16;
                }
            }
        }
        __syncthreads();   // before next chunk overwrites smem
    }

    // --- epilogue: unpack, dot = KK - 2*cnt, scale, store ---
    const float scale = xclip[0] * yclip[0];
    const int m0 = tm * 128 + tm8 * 8;
    const int n0 = tn * 128 + tn8 * 8;

    #pragma unroll
    for (int i = 0; i < 8; i++) {
        float* orow = out + ((size_t)b * MM + m0 + i) * NN + n0;
        float4 v0, v1;
        v0.x = (float)(KK - 2 * (int)(acc[i][0] & 0xFFFF)) * scale;
        v0.y = (float)(KK - 2 * (int)(acc[i][1] & 0xFFFF)) * scale;
        v0.z = (float)(KK - 2 * (int)(acc[i][2] & 0xFFFF)) * scale;
        v0.w = (float)(KK - 2 * (int)(acc[i][3] & 0xFFFF)) * scale;
        v1.x = (float)(KK - 2 * (int)(acc[i][0] >> 16)) * scale;
        v1.y = (float)(KK - 2 * (int)(acc[i][1] >> 16)) * scale;
        v1.z = (float)(KK - 2 * (int)(acc[i][2] >> 16)) * scale;
        v1.w = (float)(KK - 2 * (int)(acc[i][3] >> 16)) * scale;
        *reinterpret_cast<float4*>(orow)     = v0;
        *reinterpret_cast<float4*>(orow + 4) = v1;
    }
}

// ---------------------------------------------------------------------------
// Launch
// ---------------------------------------------------------------------------
extern "C" void kernel_launch(void* const* d_in, const int* in_sizes, int n_in,
                              void* d_out, int out_size) {
    const float* x     = (const float*)d_in[0];
    const float* y     = (const float*)d_in[1];
    const float* xclip = (const float*)d_in[2];
    const float* yclip = (const float*)d_in[3];
    float* out = (float*)d_out;

    uint32_t *xb, *yb;
    cudaGetSymbolAddress((void**)&xb, g_xb);
    cudaGetSymbolAddress((void**)&yb, g_yb);

    const int nwords = BB * KW * MM;                    // 1,048,576 per tensor
    pack_bits2<<<(2 * nwords + 255) / 256, 256>>>(x, y, xb, yb, nwords);

    cudaFuncSetAttribute(bingemm_popc, cudaFuncAttributeMaxDynamicSharedMemorySize, SMEM_TOTAL);
    dim3 grid(NN / 128, MM / 128, BB);
    bingemm_popc<<<grid, 256, SMEM_TOTAL>>>(xclip, yclip, out);
}